// round 1
// baseline (speedup 1.0000x reference)
#include <cuda_runtime.h>

#define NTOK 4096
#define CDIM 256
#define FDIM 64
#define BATCH 8

// Scratch (allocation-free rule: __device__ globals)
__device__ float g_f[BATCH * NTOK * FDIM];   // 8 MB
__device__ float g_g[BATCH * NTOK * FDIM];   // 8 MB
__device__ float g_h[BATCH * NTOK * CDIM];   // 32 MB
__device__ float g_o[BATCH * NTOK * CDIM];   // 32 MB

// ---------------------------------------------------------------------------
// Generic 64x64-tile GEMM: C[M,N] = A[M,K] @ W[K,N]
// MODE 0/1/2: C = g_f / g_g / g_h.  MODE 3: A = g_o, C = out, epilogue
//             C = gamma*acc + X (residual).
// 256 threads, 4x4 micro-tile per thread, BK=16.
// ---------------------------------------------------------------------------
template <int MODE>
__global__ __launch_bounds__(256) void gemm_k(
    const float* __restrict__ Aext, const float* __restrict__ W,
    float* __restrict__ Cext, const float* __restrict__ X,
    const float* __restrict__ gamma, int M, int K, int N)
{
    __shared__ float As[64][17];   // pad 17: scalar reads 2-way max
    __shared__ float Ws[16][64];

    const float* __restrict__ A = (MODE == 3) ? g_o : Aext;
    float* __restrict__ C =
        (MODE == 0) ? g_f : (MODE == 1) ? g_g : (MODE == 2) ? g_h : Cext;

    const int m0 = blockIdx.x * 64;
    const int n0 = blockIdx.y * 64;
    const int tid = threadIdx.x;
    const int ty = tid >> 4;       // 0..15 row group
    const int tx = tid & 15;       // 0..15 col group

    float acc[4][4];
#pragma unroll
    for (int i = 0; i < 4; i++)
#pragma unroll
        for (int j = 0; j < 4; j++) acc[i][j] = 0.0f;

    for (int k0 = 0; k0 < K; k0 += 16) {
        {
            int r = tid >> 2;
            int q = (tid & 3) << 2;
            float4 v = *(const float4*)(A + (size_t)(m0 + r) * K + k0 + q);
            As[r][q + 0] = v.x; As[r][q + 1] = v.y;
            As[r][q + 2] = v.z; As[r][q + 3] = v.w;
        }
        {
            int kr = tid >> 4;
            int cq = (tid & 15) << 2;
            *(float4*)(&Ws[kr][cq]) =
                *(const float4*)(W + (size_t)(k0 + kr) * N + n0 + cq);
        }
        __syncthreads();
#pragma unroll
        for (int k = 0; k < 16; k++) {
            float4 b = *(const float4*)(&Ws[k][tx << 2]);
#pragma unroll
            for (int i = 0; i < 4; i++) {
                float a = As[(ty << 2) + i][k];
                acc[i][0] += a * b.x; acc[i][1] += a * b.y;
                acc[i][2] += a * b.z; acc[i][3] += a * b.w;
            }
        }
        __syncthreads();
    }

    float gam = (MODE == 3) ? *gamma : 0.0f;
#pragma unroll
    for (int i = 0; i < 4; i++) {
        size_t row = (size_t)(m0 + (ty << 2) + i);
        float4 v;
        if (MODE == 3) {
            float4 xr = *(const float4*)(X + row * N + n0 + (tx << 2));
            v.x = gam * acc[i][0] + xr.x;
            v.y = gam * acc[i][1] + xr.y;
            v.z = gam * acc[i][2] + xr.z;
            v.w = gam * acc[i][3] + xr.w;
        } else {
            v.x = acc[i][0]; v.y = acc[i][1]; v.z = acc[i][2]; v.w = acc[i][3];
        }
        *(float4*)(C + row * N + n0 + (tx << 2)) = v;
    }
}

// ---------------------------------------------------------------------------
// Flash attention: per CTA one (batch, 64-row i-tile). Streams 64-row j-tiles.
// Thread layout: rg = tid>>4 owns rows rg*4..rg*4+3;
//                cg = tid&15 owns S-cols {cg+16j} and V-channels cg*16..+15.
// ---------------------------------------------------------------------------
struct AttnSmem {
    float fs[64][64];    // f i-tile            16 KB
    float gs[64][68];    // g j-tile (padded)   17 KB
    float hs[64][256];   // h j-tile            64 KB
    float ps[64][64];    // P tile              16 KB
    float redm[16][64];  // row reductions       4 KB
};

__global__ __launch_bounds__(256) void attn_k() {
    extern __shared__ char sraw[];
    AttnSmem& sm = *reinterpret_cast<AttnSmem*>(sraw);

    const int b  = blockIdx.y;
    const int i0 = blockIdx.x * 64;
    const int tid = threadIdx.x;
    const int rg = tid >> 4;
    const int cg = tid & 15;
    const int r0 = rg << 2;

    const float* __restrict__ fb = g_f + (size_t)b * NTOK * FDIM;
    const float* __restrict__ gb = g_g + (size_t)b * NTOK * FDIM;
    const float* __restrict__ hb = g_h + (size_t)b * NTOK * CDIM;

    // load f i-tile once
    for (int idx = tid; idx < 64 * 16; idx += 256) {
        int r = idx >> 4, c = (idx & 15) << 2;
        *(float4*)&sm.fs[r][c] = *(const float4*)(fb + (size_t)(i0 + r) * FDIM + c);
    }

    float4 acc[4][4];
#pragma unroll
    for (int i = 0; i < 4; i++)
#pragma unroll
        for (int q = 0; q < 4; q++) acc[i][q] = make_float4(0.f, 0.f, 0.f, 0.f);
    float m[4] = {-1e30f, -1e30f, -1e30f, -1e30f};
    float l[4] = {0.f, 0.f, 0.f, 0.f};

    for (int j0 = 0; j0 < NTOK; j0 += 64) {
        __syncthreads();  // prior tile's smem reads complete
        for (int idx = tid; idx < 64 * 16; idx += 256) {
            int r = idx >> 4, c = (idx & 15) << 2;
            *(float4*)&sm.gs[r][c] =
                *(const float4*)(gb + (size_t)(j0 + r) * FDIM + c);
        }
        for (int idx = tid; idx < 64 * 64; idx += 256) {
            int r = idx >> 6, c = (idx & 63) << 2;
            *(float4*)&sm.hs[r][c] =
                *(const float4*)(hb + (size_t)(j0 + r) * CDIM + c);
        }
        __syncthreads();

        // S = f_i @ g_j^T   (thread: 4 rows x cols {cg+16j})
        float s[4][4];
#pragma unroll
        for (int i = 0; i < 4; i++)
#pragma unroll
            for (int j = 0; j < 4; j++) s[i][j] = 0.f;

#pragma unroll 4
        for (int kk = 0; kk < 64; kk += 4) {
            float4 av[4], bv[4];
#pragma unroll
            for (int i = 0; i < 4; i++)
                av[i] = *(const float4*)&sm.fs[r0 + i][kk];
#pragma unroll
            for (int j = 0; j < 4; j++)
                bv[j] = *(const float4*)&sm.gs[cg + (j << 4)][kk];
#pragma unroll
            for (int i = 0; i < 4; i++)
#pragma unroll
                for (int j = 0; j < 4; j++) {
                    s[i][j] += av[i].x * bv[j].x;
                    s[i][j] += av[i].y * bv[j].y;
                    s[i][j] += av[i].z * bv[j].z;
                    s[i][j] += av[i].w * bv[j].w;
                }
        }

        // tile row-max -> smem reduction
#pragma unroll
        for (int i = 0; i < 4; i++) {
            float tm = fmaxf(fmaxf(s[i][0], s[i][1]), fmaxf(s[i][2], s[i][3]));
            sm.redm[cg][r0 + i] = tm;
        }
        __syncthreads();

        float alpha[4];
#pragma unroll
        for (int i = 0; i < 4; i++) {
            float mx = sm.redm[0][r0 + i];
#pragma unroll
            for (int c2 = 1; c2 < 16; c2++)
                mx = fmaxf(mx, sm.redm[c2][r0 + i]);
            float nm = fmaxf(m[i], mx);
            alpha[i] = __expf(m[i] - nm);
            m[i] = nm;
        }

        // P = exp(S - m), partial row-sums kept per-thread (linear in rescale)
#pragma unroll
        for (int i = 0; i < 4; i++) {
            float tl = 0.f;
#pragma unroll
            for (int j = 0; j < 4; j++) {
                float p = __expf(s[i][j] - m[i]);
                sm.ps[r0 + i][cg + (j << 4)] = p;
                tl += p;
            }
            l[i] = l[i] * alpha[i] + tl;
        }
        __syncthreads();

        // rescale accumulators
#pragma unroll
        for (int i = 0; i < 4; i++) {
            float a = alpha[i];
#pragma unroll
            for (int q = 0; q < 4; q++) {
                acc[i][q].x *= a; acc[i][q].y *= a;
                acc[i][q].z *= a; acc[i][q].w *= a;
            }
        }

        // acc += P @ h_j   (thread: 4 rows x 16 channels at cg*16)
#pragma unroll 1
        for (int j4 = 0; j4 < 64; j4 += 4) {
            float4 pr[4];
#pragma unroll
            for (int i = 0; i < 4; i++)
                pr[i] = *(const float4*)&sm.ps[r0 + i][j4];
#pragma unroll
            for (int jj = 0; jj < 4; jj++) {
                float4 hv[4];
#pragma unroll
                for (int q = 0; q < 4; q++)
                    hv[q] = *(const float4*)&sm.hs[j4 + jj][(cg << 4) + (q << 2)];
                float pj[4];
                pj[0] = (jj == 0) ? pr[0].x : (jj == 1) ? pr[0].y : (jj == 2) ? pr[0].z : pr[0].w;
                pj[1] = (jj == 0) ? pr[1].x : (jj == 1) ? pr[1].y : (jj == 2) ? pr[1].z : pr[1].w;
                pj[2] = (jj == 0) ? pr[2].x : (jj == 1) ? pr[2].y : (jj == 2) ? pr[2].z : pr[2].w;
                pj[3] = (jj == 0) ? pr[3].x : (jj == 1) ? pr[3].y : (jj == 2) ? pr[3].z : pr[3].w;
#pragma unroll
                for (int i = 0; i < 4; i++)
#pragma unroll
                    for (int q = 0; q < 4; q++) {
                        acc[i][q].x += pj[i] * hv[q].x;
                        acc[i][q].y += pj[i] * hv[q].y;
                        acc[i][q].z += pj[i] * hv[q].z;
                        acc[i][q].w += pj[i] * hv[q].w;
                    }
            }
        }
    }

    // final l reduction (reuse redm) and write o
    __syncthreads();
#pragma unroll
    for (int i = 0; i < 4; i++) sm.redm[cg][r0 + i] = l[i];
    __syncthreads();
#pragma unroll
    for (int i = 0; i < 4; i++) {
        float ls = 0.f;
#pragma unroll
        for (int c2 = 0; c2 < 16; c2++) ls += sm.redm[c2][r0 + i];
        float inv = 1.0f / ls;
        float* op = g_o + ((size_t)b * NTOK + i0 + r0 + i) * CDIM + (cg << 4);
#pragma unroll
        for (int q = 0; q < 4; q++) {
            float4 v = acc[i][q];
            v.x *= inv; v.y *= inv; v.z *= inv; v.w *= inv;
            *(float4*)(op + (q << 2)) = v;
        }
    }
}

// ---------------------------------------------------------------------------
extern "C" void kernel_launch(void* const* d_in, const int* in_sizes, int n_in,
                              void* d_out, int out_size) {
    const float* x     = (const float*)d_in[0];   // [8,64,64,256]
    const float* Wf    = (const float*)d_in[1];   // [1,1,256,64]
    const float* Wg    = (const float*)d_in[2];   // [1,1,256,64]
    const float* Wh    = (const float*)d_in[3];   // [1,1,256,256]
    const float* Wv    = (const float*)d_in[4];   // [1,1,256,256]
    const float* gamma = (const float*)d_in[5];   // [1]
    float* out = (float*)d_out;

    const int M = BATCH * NTOK;  // 32768

    // projections
    gemm_k<0><<<dim3(M / 64, 1), 256>>>(x, Wf, nullptr, nullptr, nullptr, M, CDIM, FDIM);
    gemm_k<1><<<dim3(M / 64, 1), 256>>>(x, Wg, nullptr, nullptr, nullptr, M, CDIM, FDIM);
    gemm_k<2><<<dim3(M / 64, 4), 256>>>(x, Wh, nullptr, nullptr, nullptr, M, CDIM, CDIM);

    // fused attention
    static_assert(sizeof(AttnSmem) <= 128 * 1024, "smem");
    cudaFuncSetAttribute(attn_k, cudaFuncAttributeMaxDynamicSharedMemorySize,
                         (int)sizeof(AttnSmem));
    attn_k<<<dim3(NTOK / 64, BATCH), 256, sizeof(AttnSmem)>>>();

    // out = gamma*(o @ Wv) + x
    gemm_k<3><<<dim3(M / 64, 4), 256>>>(nullptr, Wv, out, x, gamma, M, CDIM, CDIM);
}